// round 1
// baseline (speedup 1.0000x reference)
#include <cuda_runtime.h>
#include <math.h>

#define BB   2
#define LL   2048
#define DD   1024
#define HH   16
#define DHH  64
#define NN3  3072
#define SCALEF 0.125f
#define EPSV 1e-10f
#define NEG_BIG (-1e30f)

// Scratch (static device globals; no runtime allocation allowed)
__device__ float g_q [BB*HH*LL*DHH];   // [b,h,l,dh]
__device__ float g_kT[BB*HH*DHH*LL];   // [b,h,dh,l]  (K transposed for attention)
__device__ float g_v [BB*HH*LL*DHH];   // [b,h,l,dh]
__device__ float g_z [BB*LL*DD];       // [b,l,inner]

// ---------------------------------------------------------------------------
// Kernel 1: QKV projection  y = x @ W_qkv, scatter into g_q / g_kT / g_v
// M=4096 (b*l), N=3072, K=1024.  128x128x16 tiles, 256 thr, 8x8 per thread.
// ---------------------------------------------------------------------------
__global__ __launch_bounds__(256) void qkv_kernel(const float* __restrict__ x,
                                                  const float* __restrict__ W) {
    __shared__ float As[16][132];
    __shared__ float Bs[16][132];
    const int bn = blockIdx.x;          // 24
    const int bm = blockIdx.y;          // 32
    const int tid = threadIdx.x;
    const int tx = tid & 15, ty = tid >> 4;

    float acc[8][8];
    #pragma unroll
    for (int i = 0; i < 8; i++)
        #pragma unroll
        for (int j = 0; j < 8; j++) acc[i][j] = 0.f;

    const float* xA = x + (size_t)(bm * 128) * DD;
    const float* WB = W + bn * 128;

    for (int k0 = 0; k0 < DD; k0 += 16) {
        #pragma unroll
        for (int it = 0; it < 2; it++) {
            int idx = tid + it * 256;
            int r = idx >> 2, c = (idx & 3) << 2;
            float4 v = *(const float4*)&xA[(size_t)r * DD + k0 + c];
            As[c + 0][r] = v.x; As[c + 1][r] = v.y;
            As[c + 2][r] = v.z; As[c + 3][r] = v.w;
        }
        #pragma unroll
        for (int it = 0; it < 2; it++) {
            int idx = tid + it * 256;
            int r = idx >> 5, c = (idx & 31) << 2;
            *(float4*)&Bs[r][c] = *(const float4*)&WB[(size_t)(k0 + r) * NN3 + c];
        }
        __syncthreads();
        #pragma unroll
        for (int kk = 0; kk < 16; kk++) {
            float a[8], b[8];
            *(float4*)(a)     = *(float4*)&As[kk][ty * 4];
            *(float4*)(a + 4) = *(float4*)&As[kk][64 + ty * 4];
            *(float4*)(b)     = *(float4*)&Bs[kk][tx * 4];
            *(float4*)(b + 4) = *(float4*)&Bs[kk][64 + tx * 4];
            #pragma unroll
            for (int i = 0; i < 8; i++)
                #pragma unroll
                for (int j = 0; j < 8; j++) acc[i][j] += a[i] * b[j];
        }
        __syncthreads();
    }

    // scatter: n -> (s, h, d), m -> (b, l)
    #pragma unroll
    for (int ch = 0; ch < 2; ch++) {
        int n0 = bn * 128 + ch * 64 + tx * 4;
        int s  = n0 >> 10;
        int h  = (n0 >> 6) & 15;
        int d0 = n0 & 63;
        #pragma unroll
        for (int rh = 0; rh < 2; rh++) {
            #pragma unroll
            for (int i = 0; i < 4; i++) {
                int m  = bm * 128 + rh * 64 + ty * 4 + i;
                int b_ = m >> 11;
                int l  = m & 2047;
                int ai = rh * 4 + i;
                if (s != 1) {
                    float* dst = (s == 0 ? g_q : g_v)
                               + (((size_t)(b_ * HH + h) * LL + l) * DHH + d0);
                    *(float4*)dst = make_float4(acc[ai][ch*4+0], acc[ai][ch*4+1],
                                                acc[ai][ch*4+2], acc[ai][ch*4+3]);
                } else {
                    #pragma unroll
                    for (int j = 0; j < 4; j++)
                        g_kT[((size_t)(b_ * HH + h) * DHH + d0 + j) * LL + l]
                            = acc[ai][ch*4+j];
                }
            }
        }
    }
}

// ---------------------------------------------------------------------------
// Kernel 2: flash attention with multiplicative mask + renorm.
// One block = (b, h, 64-query tile). 256 threads, 4x4 microtiles.
// out_ij = e_ij * mask_ij / (sum_j e_ij*mask_ij + eps * sum_j e_ij)
// ---------------------------------------------------------------------------
__global__ __launch_bounds__(256) void attn_kernel(const float* __restrict__ mask) {
    extern __shared__ float sm[];
    float* Qts  = sm;                        // [64][68]  (d, i), scale folded
    float* Kts  = sm + 64 * 68;              // [64][68]  (d, j)
    float* Vs   = sm + 2 * 64 * 68;          // [64][64]  (j, d)
    float* Ss   = sm + 2 * 64 * 68 + 64*64;  // [64][68]  (i, j)
    float* m_s  = Ss + 64 * 68;
    float* f_s  = m_s + 64;
    float* zall = f_s + 64;
    float* zm   = zall + 64;

    const int bi  = blockIdx.x;   // 32 query tiles
    const int h   = blockIdx.y;   // 16
    const int b_  = blockIdx.z;   // 2
    const int tid = threadIdx.x;
    const int tx = tid & 15, ty = tid >> 4;
    const int bh = b_ * HH + h;

    const float* Qbase = g_q  + ((size_t)bh * LL + bi * 64) * DHH;
    const float* KTb   = g_kT + (size_t)bh * DHH * LL;
    const float* Vb    = g_v  + (size_t)bh * LL * DHH;
    const float* Mb    = mask + ((size_t)b_ * LL + bi * 64) * LL;

    // Load Q tile transposed into smem, folding the 1/sqrt(dh) scale.
    #pragma unroll
    for (int it = 0; it < 4; it++) {
        int idx = tid + it * 256;
        int r = idx >> 4, c = (idx & 15) << 2;
        float4 v = *(const float4*)&Qbase[r * DHH + c];
        Qts[(c + 0) * 68 + r] = v.x * SCALEF;
        Qts[(c + 1) * 68 + r] = v.y * SCALEF;
        Qts[(c + 2) * 68 + r] = v.z * SCALEF;
        Qts[(c + 3) * 68 + r] = v.w * SCALEF;
    }
    if (tid < 64) { m_s[tid] = NEG_BIG; zall[tid] = 0.f; zm[tid] = 0.f; }

    float acc[4][4];
    #pragma unroll
    for (int i = 0; i < 4; i++)
        #pragma unroll
        for (int j = 0; j < 4; j++) acc[i][j] = 0.f;
    __syncthreads();

    for (int jt = 0; jt < 32; jt++) {
        const int j0 = jt * 64;
        // Load K (already transposed in gmem) and V tiles.
        #pragma unroll
        for (int it = 0; it < 4; it++) {
            int idx = tid + it * 256;
            int d = idx >> 4, c = (idx & 15) << 2;
            *(float4*)&Kts[d * 68 + c] = *(const float4*)&KTb[(size_t)d * LL + j0 + c];
            *(float4*)&Vs [d * 64 + c] = *(const float4*)&Vb [(size_t)(j0 + d) * DHH + c];
        }
        __syncthreads();

        // S = (Q*scale) @ K^T
        float s4[4][4];
        #pragma unroll
        for (int i = 0; i < 4; i++)
            #pragma unroll
            for (int j = 0; j < 4; j++) s4[i][j] = 0.f;
        #pragma unroll 16
        for (int d = 0; d < 64; d++) {
            float q[4], k[4];
            *(float4*)q = *(float4*)&Qts[d * 68 + ty * 4];
            *(float4*)k = *(float4*)&Kts[d * 68 + tx * 4];
            #pragma unroll
            for (int i = 0; i < 4; i++)
                #pragma unroll
                for (int j = 0; j < 4; j++) s4[i][j] += q[i] * k[j];
        }
        #pragma unroll
        for (int i = 0; i < 4; i++)
            *(float4*)&Ss[(ty * 4 + i) * 68 + tx * 4]
                = make_float4(s4[i][0], s4[i][1], s4[i][2], s4[i][3]);
        __syncthreads();

        // Row max update (4 lanes per row)
        {
            int r = tid >> 2, part = tid & 3;
            const float* row = &Ss[r * 68 + part * 16];
            float mx = NEG_BIG;
            #pragma unroll
            for (int c = 0; c < 16; c++) mx = fmaxf(mx, row[c]);
            mx = fmaxf(mx, __shfl_xor_sync(0xffffffffu, mx, 1));
            mx = fmaxf(mx, __shfl_xor_sync(0xffffffffu, mx, 2));
            if (part == 0) {
                float mold = m_s[r];
                float mnew = fmaxf(mold, mx);
                float f = __expf(mold - mnew);
                f_s[r] = f;
                m_s[r] = mnew;
                zall[r] *= f;
                zm[r]   *= f;
            }
        }
        __syncthreads();

        // Exponentiate, apply mask, accumulate both partition sums.
        {
            int r = tid >> 2, part = tid & 3;
            float mrow = m_s[r];
            float* row = &Ss[r * 68 + part * 16];
            const float* mk = Mb + (size_t)r * LL + j0 + part * 16;
            float za = 0.f, zp = 0.f;
            #pragma unroll
            for (int c = 0; c < 16; c++) {
                float e = __expf(row[c] - mrow);
                za += e;
                float p = e * mk[c];
                row[c] = p;
                zp += p;
            }
            za += __shfl_xor_sync(0xffffffffu, za, 1);
            za += __shfl_xor_sync(0xffffffffu, za, 2);
            zp += __shfl_xor_sync(0xffffffffu, zp, 1);
            zp += __shfl_xor_sync(0xffffffffu, zp, 2);
            if (part == 0) { zall[r] += za; zm[r] += zp; }
        }
        __syncthreads();

        // O = O * f + P @ V
        {
            float fr[4];
            #pragma unroll
            for (int i = 0; i < 4; i++) fr[i] = f_s[ty * 4 + i];
            #pragma unroll
            for (int i = 0; i < 4; i++)
                #pragma unroll
                for (int j = 0; j < 4; j++) acc[i][j] *= fr[i];
            #pragma unroll 4
            for (int j4 = 0; j4 < 64; j4 += 4) {
                float p[4][4];
                #pragma unroll
                for (int i = 0; i < 4; i++)
                    *(float4*)p[i] = *(float4*)&Ss[(ty * 4 + i) * 68 + j4];
                #pragma unroll
                for (int jj = 0; jj < 4; jj++) {
                    float v4[4];
                    *(float4*)v4 = *(float4*)&Vs[(j4 + jj) * 64 + tx * 4];
                    #pragma unroll
                    for (int i = 0; i < 4; i++)
                        #pragma unroll
                        for (int dd = 0; dd < 4; dd++)
                            acc[i][dd] += p[i][jj] * v4[dd];
                }
            }
        }
        __syncthreads();
    }

    // Epilogue: divide by (zm + eps*zall), write [b, l, h*64+d]
    #pragma unroll
    for (int i = 0; i < 4; i++) {
        int r = ty * 4 + i;
        float inv = 1.f / (zm[r] + EPSV * zall[r]);
        int gi = bi * 64 + r;
        *(float4*)&g_z[((size_t)b_ * LL + gi) * DD + h * DHH + tx * 4]
            = make_float4(acc[i][0] * inv, acc[i][1] * inv,
                          acc[i][2] * inv, acc[i][3] * inv);
    }
}

// ---------------------------------------------------------------------------
// Kernel 3: output projection  out = g_z @ W_out + b_out
// M=4096, N=1024, K=1024. Same tiling as kernel 1.
// ---------------------------------------------------------------------------
__global__ __launch_bounds__(256) void out_kernel(const float* __restrict__ W,
                                                  const float* __restrict__ bias,
                                                  float* __restrict__ out) {
    __shared__ float As[16][132];
    __shared__ float Bs[16][132];
    const int bn = blockIdx.x;          // 8
    const int bm = blockIdx.y;          // 32
    const int tid = threadIdx.x;
    const int tx = tid & 15, ty = tid >> 4;

    float acc[8][8];
    #pragma unroll
    for (int i = 0; i < 8; i++)
        #pragma unroll
        for (int j = 0; j < 8; j++) acc[i][j] = 0.f;

    const float* xA = g_z + (size_t)(bm * 128) * DD;
    const float* WB = W + bn * 128;

    for (int k0 = 0; k0 < DD; k0 += 16) {
        #pragma unroll
        for (int it = 0; it < 2; it++) {
            int idx = tid + it * 256;
            int r = idx >> 2, c = (idx & 3) << 2;
            float4 v = *(const float4*)&xA[(size_t)r * DD + k0 + c];
            As[c + 0][r] = v.x; As[c + 1][r] = v.y;
            As[c + 2][r] = v.z; As[c + 3][r] = v.w;
        }
        #pragma unroll
        for (int it = 0; it < 2; it++) {
            int idx = tid + it * 256;
            int r = idx >> 5, c = (idx & 31) << 2;
            *(float4*)&Bs[r][c] = *(const float4*)&WB[(size_t)(k0 + r) * DD + c];
        }
        __syncthreads();
        #pragma unroll
        for (int kk = 0; kk < 16; kk++) {
            float a[8], b[8];
            *(float4*)(a)     = *(float4*)&As[kk][ty * 4];
            *(float4*)(a + 4) = *(float4*)&As[kk][64 + ty * 4];
            *(float4*)(b)     = *(float4*)&Bs[kk][tx * 4];
            *(float4*)(b + 4) = *(float4*)&Bs[kk][64 + tx * 4];
            #pragma unroll
            for (int i = 0; i < 8; i++)
                #pragma unroll
                for (int j = 0; j < 8; j++) acc[i][j] += a[i] * b[j];
        }
        __syncthreads();
    }

    #pragma unroll
    for (int ch = 0; ch < 2; ch++) {
        int n0 = bn * 128 + ch * 64 + tx * 4;
        float4 bv = *(const float4*)&bias[n0];
        #pragma unroll
        for (int rh = 0; rh < 2; rh++) {
            #pragma unroll
            for (int i = 0; i < 4; i++) {
                int m  = bm * 128 + rh * 64 + ty * 4 + i;
                int ai = rh * 4 + i;
                *(float4*)&out[(size_t)m * DD + n0]
                    = make_float4(acc[ai][ch*4+0] + bv.x, acc[ai][ch*4+1] + bv.y,
                                  acc[ai][ch*4+2] + bv.z, acc[ai][ch*4+3] + bv.w);
            }
        }
    }
}

// ---------------------------------------------------------------------------
extern "C" void kernel_launch(void* const* d_in, const int* in_sizes, int n_in,
                              void* d_out, int out_size) {
    const float* x    = (const float*)d_in[0];
    const float* mask = (const float*)d_in[1];
    const float* Wqkv = (const float*)d_in[2];
    const float* Wout = (const float*)d_in[3];
    const float* bout = (const float*)d_in[4];
    float* out = (float*)d_out;

    const int attn_smem = (2 * 64 * 68 + 64 * 64 + 64 * 68 + 256) * 4;  // 69632 B
    cudaFuncSetAttribute(attn_kernel,
                         cudaFuncAttributeMaxDynamicSharedMemorySize, attn_smem);

    dim3 g1(NN3 / 128, (BB * LL) / 128);
    qkv_kernel<<<g1, 256>>>(x, Wqkv);

    dim3 g2(LL / 64, HH, BB);
    attn_kernel<<<g2, 256, attn_smem>>>(mask);

    dim3 g3(DD / 128, (BB * LL) / 128);
    out_kernel<<<g3, 256>>>(Wout, bout, out);
}

// round 4
// speedup vs baseline: 1.5964x; 1.5964x over previous
#include <cuda_runtime.h>
#include <math.h>
#include <stdint.h>

#define BB   2
#define LL   2048
#define DD   1024
#define HH   16
#define DHH  64
#define NN3  3072
#define SCALEF 0.125f
#define EPSV 1e-10f
#define NEG_BIG (-1e30f)

// Scratch (static device globals; no runtime allocation allowed)
__device__ float g_q [BB*HH*LL*DHH];   // [b,h,l,dh]
__device__ float g_kT[BB*HH*DHH*LL];   // [b,h,dh,l]  (K transposed for attention)
__device__ float g_v [BB*HH*LL*DHH];   // [b,h,l,dh]
__device__ float g_z [BB*LL*DD];       // [b,l,inner]

// ---------------------------------------------------------------------------
// TF32 helpers
// ---------------------------------------------------------------------------
__device__ __forceinline__ uint32_t f2tf(float f) {
    uint32_t u;
    asm("cvt.rna.tf32.f32 %0, %1;" : "=r"(u) : "f"(f));
    return u;
}

__device__ __forceinline__ void mma_tf32(float* c, const uint32_t* a, const uint32_t* b) {
    asm volatile(
        "mma.sync.aligned.m16n8k8.row.col.f32.tf32.tf32.f32 "
        "{%0,%1,%2,%3}, {%4,%5,%6,%7}, {%8,%9}, {%0,%1,%2,%3};"
        : "+f"(c[0]), "+f"(c[1]), "+f"(c[2]), "+f"(c[3])
        : "r"(a[0]), "r"(a[1]), "r"(a[2]), "r"(a[3]), "r"(b[0]), "r"(b[1]));
}

// ---------------------------------------------------------------------------
// Kernel 1: QKV projection  y = x @ W_qkv, scatter into g_q / g_kT / g_v
// M=4096 (b*l), N=3072, K=1024.  128x128x16 tiles, 256 thr, 8x8 per thread.
// ---------------------------------------------------------------------------
__global__ __launch_bounds__(256) void qkv_kernel(const float* __restrict__ x,
                                                  const float* __restrict__ W) {
    __shared__ float As[16][132];
    __shared__ float Bs[16][132];
    const int bn = blockIdx.x;          // 24
    const int bm = blockIdx.y;          // 32
    const int tid = threadIdx.x;
    const int tx = tid & 15, ty = tid >> 4;

    float acc[8][8];
    #pragma unroll
    for (int i = 0; i < 8; i++)
        #pragma unroll
        for (int j = 0; j < 8; j++) acc[i][j] = 0.f;

    const float* xA = x + (size_t)(bm * 128) * DD;
    const float* WB = W + bn * 128;

    for (int k0 = 0; k0 < DD; k0 += 16) {
        #pragma unroll
        for (int it = 0; it < 2; it++) {
            int idx = tid + it * 256;
            int r = idx >> 2, c = (idx & 3) << 2;
            float4 v = *(const float4*)&xA[(size_t)r * DD + k0 + c];
            As[c + 0][r] = v.x; As[c + 1][r] = v.y;
            As[c + 2][r] = v.z; As[c + 3][r] = v.w;
        }
        #pragma unroll
        for (int it = 0; it < 2; it++) {
            int idx = tid + it * 256;
            int r = idx >> 5, c = (idx & 31) << 2;
            *(float4*)&Bs[r][c] = *(const float4*)&WB[(size_t)(k0 + r) * NN3 + c];
        }
        __syncthreads();
        #pragma unroll
        for (int kk = 0; kk < 16; kk++) {
            float a[8], b[8];
            *(float4*)(a)     = *(float4*)&As[kk][ty * 4];
            *(float4*)(a + 4) = *(float4*)&As[kk][64 + ty * 4];
            *(float4*)(b)     = *(float4*)&Bs[kk][tx * 4];
            *(float4*)(b + 4) = *(float4*)&Bs[kk][64 + tx * 4];
            #pragma unroll
            for (int i = 0; i < 8; i++)
                #pragma unroll
                for (int j = 0; j < 8; j++) acc[i][j] += a[i] * b[j];
        }
        __syncthreads();
    }

    // scatter: n -> (s, h, d), m -> (b, l)
    #pragma unroll
    for (int ch = 0; ch < 2; ch++) {
        int n0 = bn * 128 + ch * 64 + tx * 4;
        int s  = n0 >> 10;
        int h  = (n0 >> 6) & 15;
        int d0 = n0 & 63;
        #pragma unroll
        for (int rh = 0; rh < 2; rh++) {
            #pragma unroll
            for (int i = 0; i < 4; i++) {
                int m  = bm * 128 + rh * 64 + ty * 4 + i;
                int b_ = m >> 11;
                int l  = m & 2047;
                int ai = rh * 4 + i;
                if (s != 1) {
                    float* dst = (s == 0 ? g_q : g_v)
                               + (((size_t)(b_ * HH + h) * LL + l) * DHH + d0);
                    *(float4*)dst = make_float4(acc[ai][ch*4+0], acc[ai][ch*4+1],
                                                acc[ai][ch*4+2], acc[ai][ch*4+3]);
                } else {
                    #pragma unroll
                    for (int j = 0; j < 4; j++)
                        g_kT[((size_t)(b_ * HH + h) * DHH + d0 + j) * LL + l]
                            = acc[ai][ch*4+j];
                }
            }
        }
    }
}

// ---------------------------------------------------------------------------
// Kernel 2: flash attention, TF32 mma.sync path.
// One block = (b, h, 64-query tile). 128 threads = 4 warps, each warp owns
// 16 query rows. jtile = 64 keys. Online softmax entirely in registers.
// out_ij = e_ij*mask_ij / (sum_j e_ij*mask_ij + eps * sum_j e_ij)
// ---------------------------------------------------------------------------
#define KVPAD 72   // K/V smem stride: b-frag reads hit 32 distinct banks
#define SPAD  68   // P/S smem stride: a-frag reads conflict-free

__global__ __launch_bounds__(128) void attn_kernel(const float* __restrict__ mask) {
    extern __shared__ float smf[];
    float* Ks = smf;                    // [64][72] tf32 bits, row = d
    float* Vs = smf + 64 * KVPAD;       // [64][72] tf32 bits, row = j
    float* Ss = smf + 2 * 64 * KVPAD;   // [64][68] Q staging / per-warp P tile

    const int bi  = blockIdx.x;   // 32 query tiles
    const int h   = blockIdx.y;   // 16
    const int b_  = blockIdx.z;   // 2
    const int tid = threadIdx.x;
    const int wid = tid >> 5, lane = tid & 31;
    const int g = lane >> 2, q = lane & 3;
    const int bh = b_ * HH + h;
    const int i0 = wid * 16;

    const float* Qb  = g_q  + ((size_t)bh * LL + bi * 64) * DHH;
    const float* KTb = g_kT + (size_t)bh * DHH * LL;
    const float* Vb  = g_v  + (size_t)bh * LL * DHH;
    const float* Mb  = mask + ((size_t)b_ * LL + bi * 64) * LL;

    // Stage Q (scale folded) into Ss, then pull A-fragments into registers.
    #pragma unroll
    for (int it = 0; it < 8; it++) {
        int idx = tid + it * 128;             // 1024 float4s = 64x64
        int r = idx >> 4, c4 = (idx & 15) << 2;
        float4 v = *(const float4*)&Qb[r * DHH + c4];
        Ss[r * SPAD + c4 + 0] = v.x * SCALEF;
        Ss[r * SPAD + c4 + 1] = v.y * SCALEF;
        Ss[r * SPAD + c4 + 2] = v.z * SCALEF;
        Ss[r * SPAD + c4 + 3] = v.w * SCALEF;
    }
    __syncthreads();

    uint32_t qa[8][4];
    #pragma unroll
    for (int kc = 0; kc < 8; kc++) {
        qa[kc][0] = f2tf(Ss[(i0 + g)     * SPAD + kc * 8 + q]);
        qa[kc][1] = f2tf(Ss[(i0 + g + 8) * SPAD + kc * 8 + q]);
        qa[kc][2] = f2tf(Ss[(i0 + g)     * SPAD + kc * 8 + q + 4]);
        qa[kc][3] = f2tf(Ss[(i0 + g + 8) * SPAD + kc * 8 + q + 4]);
    }
    // (Ss reuse for P is ordered behind the first in-loop __syncthreads.)

    float o[8][4];
    #pragma unroll
    for (int n = 0; n < 8; n++)
        #pragma unroll
        for (int k = 0; k < 4; k++) o[n][k] = 0.f;
    float mrow0 = NEG_BIG, mrow1 = NEG_BIG;
    float za0 = 0.f, za1 = 0.f, zp0 = 0.f, zp1 = 0.f;

    for (int jt = 0; jt < 32; jt++) {
        const int j0 = jt * 64;

        // Load K (already [d][l] in gmem) and V tiles, converting to tf32.
        #pragma unroll
        for (int it = 0; it < 8; it++) {
            int idx = tid + it * 128;
            int r = idx >> 4, c4 = (idx & 15) << 2;
            float4 kv = *(const float4*)&KTb[(size_t)r * LL + j0 + c4];
            float4 vv = *(const float4*)&Vb[(size_t)(j0 + r) * DHH + c4];
            uint32_t* kd = (uint32_t*)&Ks[r * KVPAD + c4];
            kd[0] = f2tf(kv.x); kd[1] = f2tf(kv.y);
            kd[2] = f2tf(kv.z); kd[3] = f2tf(kv.w);
            uint32_t* vd = (uint32_t*)&Vs[r * KVPAD + c4];
            vd[0] = f2tf(vv.x); vd[1] = f2tf(vv.y);
            vd[2] = f2tf(vv.z); vd[3] = f2tf(vv.w);
        }
        __syncthreads();

        // S = (Q*scale) @ K^T  : warp computes 16x64.
        float s[8][4];
        #pragma unroll
        for (int n = 0; n < 8; n++)
            #pragma unroll
            for (int k = 0; k < 4; k++) s[n][k] = 0.f;
        const uint32_t* Ku = (const uint32_t*)Ks;
        #pragma unroll
        for (int kc = 0; kc < 8; kc++) {
            #pragma unroll
            for (int n = 0; n < 8; n++) {
                uint32_t b2[2];
                b2[0] = Ku[(kc * 8 + q)     * KVPAD + n * 8 + g];
                b2[1] = Ku[(kc * 8 + q + 4) * KVPAD + n * 8 + g];
                mma_tf32(s[n], qa[kc], b2);
            }
        }

        // Row maxes (rows i0+g and i0+g+8).
        float mx0 = NEG_BIG, mx1 = NEG_BIG;
        #pragma unroll
        for (int n = 0; n < 8; n++) {
            mx0 = fmaxf(mx0, fmaxf(s[n][0], s[n][1]));
            mx1 = fmaxf(mx1, fmaxf(s[n][2], s[n][3]));
        }
        mx0 = fmaxf(mx0, __shfl_xor_sync(0xffffffffu, mx0, 1));
        mx0 = fmaxf(mx0, __shfl_xor_sync(0xffffffffu, mx0, 2));
        mx1 = fmaxf(mx1, __shfl_xor_sync(0xffffffffu, mx1, 1));
        mx1 = fmaxf(mx1, __shfl_xor_sync(0xffffffffu, mx1, 2));
        float mn0 = fmaxf(mrow0, mx0), mn1 = fmaxf(mrow1, mx1);
        float f0 = __expf(mrow0 - mn0), f1 = __expf(mrow1 - mn1);
        mrow0 = mn0; mrow1 = mn1;
        za0 *= f0; zp0 *= f0; za1 *= f1; zp1 *= f1;
        #pragma unroll
        for (int n = 0; n < 8; n++) {
            o[n][0] *= f0; o[n][1] *= f0;
            o[n][2] *= f1; o[n][3] *= f1;
        }

        // exp, mask (direct gmem LDG.64), partition sums; P -> smem (tf32).
        const float* M0 = Mb + (size_t)(i0 + g)     * LL + j0;
        const float* M1 = Mb + (size_t)(i0 + g + 8) * LL + j0;
        float sa0 = 0.f, sa1 = 0.f, sp0 = 0.f, sp1 = 0.f;
        uint32_t* Su = (uint32_t*)Ss;
        #pragma unroll
        for (int n = 0; n < 8; n++) {
            float2 mk0 = __ldg((const float2*)(M0 + n * 8 + q * 2));
            float2 mk1 = __ldg((const float2*)(M1 + n * 8 + q * 2));
            float e00 = __expf(s[n][0] - mn0), e01 = __expf(s[n][1] - mn0);
            float e10 = __expf(s[n][2] - mn1), e11 = __expf(s[n][3] - mn1);
            sa0 += e00 + e01; sa1 += e10 + e11;
            uint32_t p00 = f2tf(e00 * mk0.x), p01 = f2tf(e01 * mk0.y);
            uint32_t p10 = f2tf(e10 * mk1.x), p11 = f2tf(e11 * mk1.y);
            // sum the tf32-rounded values so numerator/denominator agree
            sp0 += __uint_as_float(p00) + __uint_as_float(p01);
            sp1 += __uint_as_float(p10) + __uint_as_float(p11);
            *(uint2*)&Su[(i0 + g)     * SPAD + n * 8 + q * 2] = make_uint2(p00, p01);
            *(uint2*)&Su[(i0 + g + 8) * SPAD + n * 8 + q * 2] = make_uint2(p10, p11);
        }
        sa0 += __shfl_xor_sync(0xffffffffu, sa0, 1);
        sa0 += __shfl_xor_sync(0xffffffffu, sa0, 2);
        sa1 += __shfl_xor_sync(0xffffffffu, sa1, 1);
        sa1 += __shfl_xor_sync(0xffffffffu, sa1, 2);
        sp0 += __shfl_xor_sync(0xffffffffu, sp0, 1);
        sp0 += __shfl_xor_sync(0xffffffffu, sp0, 2);
        sp1 += __shfl_xor_sync(0xffffffffu, sp1, 1);
        sp1 += __shfl_xor_sync(0xffffffffu, sp1, 2);
        za0 += sa0; za1 += sa1; zp0 += sp0; zp1 += sp1;
        __syncwarp();

        // P A-frags (warp-local smem slice), then O += P @ V.
        uint32_t pa[8][4];
        #pragma unroll
        for (int kc = 0; kc < 8; kc++) {
            pa[kc][0] = Su[(i0 + g)     * SPAD + kc * 8 + q];
            pa[kc][1] = Su[(i0 + g + 8) * SPAD + kc * 8 + q];
            pa[kc][2] = Su[(i0 + g)     * SPAD + kc * 8 + q + 4];
            pa[kc][3] = Su[(i0 + g + 8) * SPAD + kc * 8 + q + 4];
        }
        const uint32_t* Vu = (const uint32_t*)Vs;
        #pragma unroll
        for (int kc = 0; kc < 8; kc++) {
            #pragma unroll
            for (int n = 0; n < 8; n++) {
                uint32_t b2[2];
                b2[0] = Vu[(kc * 8 + q)     * KVPAD + n * 8 + g];
                b2[1] = Vu[(kc * 8 + q + 4) * KVPAD + n * 8 + g];
                mma_tf32(o[n], pa[kc], b2);
            }
        }
        __syncthreads();
    }

    // Epilogue: divide by (zm + eps*zall), write [b, l, h*64 + d].
    float inv0 = 1.f / (zp0 + EPSV * za0);
    float inv1 = 1.f / (zp1 + EPSV * za1);
    float* Ob = g_z + ((size_t)b_ * LL + bi * 64) * DD + h * DHH;
    #pragma unroll
    for (int n = 0; n < 8; n++) {
        *(float2*)&Ob[(size_t)(i0 + g)     * DD + n * 8 + q * 2]
            = make_float2(o[n][0] * inv0, o[n][1] * inv0);
        *(float2*)&Ob[(size_t)(i0 + g + 8) * DD + n * 8 + q * 2]
            = make_float2(o[n][2] * inv1, o[n][3] * inv1);
    }
}

// ---------------------------------------------------------------------------
// Kernel 3: output projection  out = g_z @ W_out + b_out
// M=4096, N=1024, K=1024. Same tiling as kernel 1.
// ---------------------------------------------------------------------------
__global__ __launch_bounds__(256) void out_kernel(const float* __restrict__ W,
                                                  const float* __restrict__ bias,
                                                  float* __restrict__ out) {
    __shared__ float As[16][132];
    __shared__ float Bs[16][132];
    const int bn = blockIdx.x;          // 8
    const int bm = blockIdx.y;          // 32
    const int tid = threadIdx.x;
    const int tx = tid & 15, ty = tid >> 4;

    float acc[8][8];
    #pragma unroll
    for (int i = 0; i < 8; i++)
        #pragma unroll
        for (int j = 0; j < 8; j++) acc[i][j] = 0.f;

    const float* xA = g_z + (size_t)(bm * 128) * DD;
    const float* WB = W + bn * 128;

    for (int k0 = 0; k0 < DD; k0 += 16) {
        #pragma unroll
        for (int it = 0; it < 2; it++) {
            int idx = tid + it * 256;
            int r = idx >> 2, c = (idx & 3) << 2;
            float4 v = *(const float4*)&xA[(size_t)r * DD + k0 + c];
            As[c + 0][r] = v.x; As[c + 1][r] = v.y;
            As[c + 2][r] = v.z; As[c + 3][r] = v.w;
        }
        #pragma unroll
        for (int it = 0; it < 2; it++) {
            int idx = tid + it * 256;
            int r = idx >> 5, c = (idx & 31) << 2;
            *(float4*)&Bs[r][c] = *(const float4*)&WB[(size_t)(k0 + r) * DD + c];
        }
        __syncthreads();
        #pragma unroll
        for (int kk = 0; kk < 16; kk++) {
            float a[8], b[8];
            *(float4*)(a)     = *(float4*)&As[kk][ty * 4];
            *(float4*)(a + 4) = *(float4*)&As[kk][64 + ty * 4];
            *(float4*)(b)     = *(float4*)&Bs[kk][tx * 4];
            *(float4*)(b + 4) = *(float4*)&Bs[kk][64 + tx * 4];
            #pragma unroll
            for (int i = 0; i < 8; i++)
                #pragma unroll
                for (int j = 0; j < 8; j++) acc[i][j] += a[i] * b[j];
        }
        __syncthreads();
    }

    #pragma unroll
    for (int ch = 0; ch < 2; ch++) {
        int n0 = bn * 128 + ch * 64 + tx * 4;
        float4 bv = *(const float4*)&bias[n0];
        #pragma unroll
        for (int rh = 0; rh < 2; rh++) {
            #pragma unroll
            for (int i = 0; i < 4; i++) {
                int m  = bm * 128 + rh * 64 + ty * 4 + i;
                int ai = rh * 4 + i;
                *(float4*)&out[(size_t)m * DD + n0]
                    = make_float4(acc[ai][ch*4+0] + bv.x, acc[ai][ch*4+1] + bv.y,
                                  acc[ai][ch*4+2] + bv.z, acc[ai][ch*4+3] + bv.w);
            }
        }
    }
}

// ---------------------------------------------------------------------------
extern "C" void kernel_launch(void* const* d_in, const int* in_sizes, int n_in,
                              void* d_out, int out_size) {
    const float* x    = (const float*)d_in[0];
    const float* mask = (const float*)d_in[1];
    const float* Wqkv = (const float*)d_in[2];
    const float* Wout = (const float*)d_in[3];
    const float* bout = (const float*)d_in[4];
    float* out = (float*)d_out;

    const int attn_smem = (2 * 64 * KVPAD + 64 * SPAD) * 4;  // 54272 B
    cudaFuncSetAttribute(attn_kernel,
                         cudaFuncAttributeMaxDynamicSharedMemorySize, attn_smem);

    dim3 g1(NN3 / 128, (BB * LL) / 128);
    qkv_kernel<<<g1, 256>>>(x, Wqkv);

    dim3 g2(LL / 64, HH, BB);
    attn_kernel<<<g2, 128, attn_smem>>>(mask);

    dim3 g3(DD / 128, (BB * LL) / 128);
    out_kernel<<<g3, 256>>>(Wout, bout, out);
}

// round 7
// speedup vs baseline: 2.6285x; 1.6465x over previous
#include <cuda_runtime.h>
#include <math.h>
#include <stdint.h>

#define BB   2
#define LL   2048
#define DD   1024
#define HH   16
#define DHH  64
#define NN3  3072
#define SCALEF 0.125f
#define EPSV 1e-10f
#define NEG_BIG (-1e30f)

// Scratch (static device globals; no runtime allocation allowed)
__device__ float g_q [BB*HH*LL*DHH];   // [b,h,l,dh]
__device__ float g_kT[BB*HH*DHH*LL];   // [b,h,dh,l]  (K transposed for attention)
__device__ float g_v [BB*HH*LL*DHH];   // [b,h,l,dh]
__device__ float g_z [BB*LL*DD];       // [b,l,inner]

// ---------------------------------------------------------------------------
// TF32 helpers
// ---------------------------------------------------------------------------
__device__ __forceinline__ uint32_t f2tf(float f) {
    uint32_t u;
    asm("cvt.rna.tf32.f32 %0, %1;" : "=r"(u) : "f"(f));
    return u;
}

__device__ __forceinline__ void mma_tf32(float* c, const uint32_t* a, const uint32_t* b) {
    asm volatile(
        "mma.sync.aligned.m16n8k8.row.col.f32.tf32.tf32.f32 "
        "{%0,%1,%2,%3}, {%4,%5,%6,%7}, {%8,%9}, {%0,%1,%2,%3};"
        : "+f"(c[0]), "+f"(c[1]), "+f"(c[2]), "+f"(c[3])
        : "r"(a[0]), "r"(a[1]), "r"(a[2]), "r"(a[3]), "r"(b[0]), "r"(b[1]));
}

// ---------------------------------------------------------------------------
// Shared TF32 GEMM core: 128x128 block tile, ktile=32, 256 thr (8 warps 4x2),
// warp tile 32x64. A smem [128][36], B smem [32][136] (both conflict-free).
// ---------------------------------------------------------------------------
#define APAD 36
#define BPAD 136

__device__ __forceinline__ void gemm_tile_tf32(
    const float* __restrict__ Ag,    // A block base: row-major, ld = lda
    const float* __restrict__ Bg,    // B block base: row-major, ld = ldb
    int lda, int ldb, int nktiles,
    uint32_t* As, uint32_t* Bs,      // smem
    float acc[2][8][4])
{
    const int tid = threadIdx.x;
    const int wid = tid >> 5, lane = tid & 31;
    const int g = lane >> 2, q = lane & 3;
    const int wm = wid & 3, wn = wid >> 2;

    float4 ar[4], br[4];

    // Preload ktile 0
    #pragma unroll
    for (int it = 0; it < 4; it++) {
        int idx = tid + it * 256;
        ar[it] = *(const float4*)&Ag[(size_t)(idx >> 3) * lda + ((idx & 7) << 2)];
        br[it] = *(const float4*)&Bg[(size_t)(idx >> 5) * ldb + ((idx & 31) << 2)];
    }
    #pragma unroll
    for (int it = 0; it < 4; it++) {
        int idx = tid + it * 256;
        uint32_t* ad = &As[(idx >> 3) * APAD + ((idx & 7) << 2)];
        ad[0] = f2tf(ar[it].x); ad[1] = f2tf(ar[it].y);
        ad[2] = f2tf(ar[it].z); ad[3] = f2tf(ar[it].w);
        uint32_t* bd = &Bs[(idx >> 5) * BPAD + ((idx & 31) << 2)];
        bd[0] = f2tf(br[it].x); bd[1] = f2tf(br[it].y);
        bd[2] = f2tf(br[it].z); bd[3] = f2tf(br[it].w);
    }
    __syncthreads();

    for (int kt = 0; kt < nktiles; kt++) {
        if (kt + 1 < nktiles) {
            const int k0 = (kt + 1) * 32;
            #pragma unroll
            for (int it = 0; it < 4; it++) {
                int idx = tid + it * 256;
                ar[it] = *(const float4*)&Ag[(size_t)(idx >> 3) * lda + k0 + ((idx & 7) << 2)];
                br[it] = *(const float4*)&Bg[(size_t)(k0 + (idx >> 5)) * ldb + ((idx & 31) << 2)];
            }
        }
        #pragma unroll
        for (int k8 = 0; k8 < 4; k8++) {
            uint32_t a[2][4];
            #pragma unroll
            for (int mt = 0; mt < 2; mt++) {
                int r = wm * 32 + mt * 16;
                a[mt][0] = As[(r + g)     * APAD + k8 * 8 + q];
                a[mt][1] = As[(r + g + 8) * APAD + k8 * 8 + q];
                a[mt][2] = As[(r + g)     * APAD + k8 * 8 + q + 4];
                a[mt][3] = As[(r + g + 8) * APAD + k8 * 8 + q + 4];
            }
            #pragma unroll
            for (int nt = 0; nt < 8; nt++) {
                uint32_t b2[2];
                b2[0] = Bs[(k8 * 8 + q)     * BPAD + wn * 64 + nt * 8 + g];
                b2[1] = Bs[(k8 * 8 + q + 4) * BPAD + wn * 64 + nt * 8 + g];
                mma_tf32(acc[0][nt], a[0], b2);
                mma_tf32(acc[1][nt], a[1], b2);
            }
        }
        __syncthreads();
        if (kt + 1 < nktiles) {
            #pragma unroll
            for (int it = 0; it < 4; it++) {
                int idx = tid + it * 256;
                uint32_t* ad = &As[(idx >> 3) * APAD + ((idx & 7) << 2)];
                ad[0] = f2tf(ar[it].x); ad[1] = f2tf(ar[it].y);
                ad[2] = f2tf(ar[it].z); ad[3] = f2tf(ar[it].w);
                uint32_t* bd = &Bs[(idx >> 5) * BPAD + ((idx & 31) << 2)];
                bd[0] = f2tf(br[it].x); bd[1] = f2tf(br[it].y);
                bd[2] = f2tf(br[it].z); bd[3] = f2tf(br[it].w);
            }
            __syncthreads();
        }
    }
}

// ---------------------------------------------------------------------------
// Kernel 1: QKV projection (TF32 mma), scatter into g_q / g_kT / g_v
// M=4096 (b*l), N=3072, K=1024.
// ---------------------------------------------------------------------------
__global__ __launch_bounds__(256) void qkv_kernel(const float* __restrict__ x,
                                                  const float* __restrict__ W) {
    __shared__ uint32_t As[128 * APAD];
    __shared__ uint32_t Bs[32 * BPAD];
    const int bn = blockIdx.x;          // 24
    const int bm = blockIdx.y;          // 32
    const int tid = threadIdx.x;
    const int wid = tid >> 5, lane = tid & 31;
    const int g = lane >> 2, q = lane & 3;
    const int wm = wid & 3, wn = wid >> 2;

    float acc[2][8][4];
    #pragma unroll
    for (int mt = 0; mt < 2; mt++)
        #pragma unroll
        for (int nt = 0; nt < 8; nt++)
            #pragma unroll
            for (int k = 0; k < 4; k++) acc[mt][nt][k] = 0.f;

    gemm_tile_tf32(x + (size_t)(bm * 128) * DD, W + bn * 128,
                   DD, NN3, DD / 32, As, Bs, acc);

    // Scatter: n -> (s, h, d0); whole block lies in one s (1024 % 128 == 0).
    const int n_base = bn * 128 + wn * 64;
    #pragma unroll
    for (int mt = 0; mt < 2; mt++) {
        int r0 = bm * 128 + wm * 32 + mt * 16 + g;
        int b_ = r0 >> 11;
        int l  = r0 & 2047;
        #pragma unroll
        for (int nt = 0; nt < 8; nt++) {
            int n  = n_base + nt * 8 + q * 2;
            int s  = n >> 10;
            int h  = (n >> 6) & 15;
            int d0 = n & 63;
            if (s != 1) {
                float* dst = (s == 0 ? g_q : g_v)
                           + ((size_t)(b_ * HH + h) * LL + l) * DHH + d0;
                *(float2*)dst             = make_float2(acc[mt][nt][0], acc[mt][nt][1]);
                *(float2*)(dst + 8 * DHH) = make_float2(acc[mt][nt][2], acc[mt][nt][3]);
            } else {
                float* dk = g_kT + ((size_t)(b_ * HH + h) * DHH + d0) * LL + l;
                dk[0]          = acc[mt][nt][0];
                dk[LL]         = acc[mt][nt][1];
                dk[8]          = acc[mt][nt][2];
                dk[LL + 8]     = acc[mt][nt][3];
            }
        }
    }
}

// ---------------------------------------------------------------------------
// Kernel 2: flash attention, TF32 mma.sync path (unchanged from round 4).
// ---------------------------------------------------------------------------
#define KVPAD 72
#define SPAD  68

__global__ __launch_bounds__(128) void attn_kernel(const float* __restrict__ mask) {
    extern __shared__ float smf[];
    float* Ks = smf;                    // [64][72] tf32 bits, row = d
    float* Vs = smf + 64 * KVPAD;       // [64][72] tf32 bits, row = j
    float* Ss = smf + 2 * 64 * KVPAD;   // [64][68] Q staging / per-warp P tile

    const int bi  = blockIdx.x;
    const int h   = blockIdx.y;
    const int b_  = blockIdx.z;
    const int tid = threadIdx.x;
    const int wid = tid >> 5, lane = tid & 31;
    const int g = lane >> 2, q = lane & 3;
    const int bh = b_ * HH + h;
    const int i0 = wid * 16;

    const float* Qb  = g_q  + ((size_t)bh * LL + bi * 64) * DHH;
    const float* KTb = g_kT + (size_t)bh * DHH * LL;
    const float* Vb  = g_v  + (size_t)bh * LL * DHH;
    const float* Mb  = mask + ((size_t)b_ * LL + bi * 64) * LL;

    #pragma unroll
    for (int it = 0; it < 8; it++) {
        int idx = tid + it * 128;
        int r = idx >> 4, c4 = (idx & 15) << 2;
        float4 v = *(const float4*)&Qb[r * DHH + c4];
        Ss[r * SPAD + c4 + 0] = v.x * SCALEF;
        Ss[r * SPAD + c4 + 1] = v.y * SCALEF;
        Ss[r * SPAD + c4 + 2] = v.z * SCALEF;
        Ss[r * SPAD + c4 + 3] = v.w * SCALEF;
    }
    __syncthreads();

    uint32_t qa[8][4];
    #pragma unroll
    for (int kc = 0; kc < 8; kc++) {
        qa[kc][0] = f2tf(Ss[(i0 + g)     * SPAD + kc * 8 + q]);
        qa[kc][1] = f2tf(Ss[(i0 + g + 8) * SPAD + kc * 8 + q]);
        qa[kc][2] = f2tf(Ss[(i0 + g)     * SPAD + kc * 8 + q + 4]);
        qa[kc][3] = f2tf(Ss[(i0 + g + 8) * SPAD + kc * 8 + q + 4]);
    }

    float o[8][4];
    #pragma unroll
    for (int n = 0; n < 8; n++)
        #pragma unroll
        for (int k = 0; k < 4; k++) o[n][k] = 0.f;
    float mrow0 = NEG_BIG, mrow1 = NEG_BIG;
    float za0 = 0.f, za1 = 0.f, zp0 = 0.f, zp1 = 0.f;

    for (int jt = 0; jt < 32; jt++) {
        const int j0 = jt * 64;

        #pragma unroll
        for (int it = 0; it < 8; it++) {
            int idx = tid + it * 128;
            int r = idx >> 4, c4 = (idx & 15) << 2;
            float4 kv = *(const float4*)&KTb[(size_t)r * LL + j0 + c4];
            float4 vv = *(const float4*)&Vb[(size_t)(j0 + r) * DHH + c4];
            uint32_t* kd = (uint32_t*)&Ks[r * KVPAD + c4];
            kd[0] = f2tf(kv.x); kd[1] = f2tf(kv.y);
            kd[2] = f2tf(kv.z); kd[3] = f2tf(kv.w);
            uint32_t* vd = (uint32_t*)&Vs[r * KVPAD + c4];
            vd[0] = f2tf(vv.x); vd[1] = f2tf(vv.y);
            vd[2] = f2tf(vv.z); vd[3] = f2tf(vv.w);
        }
        __syncthreads();

        float s[8][4];
        #pragma unroll
        for (int n = 0; n < 8; n++)
            #pragma unroll
            for (int k = 0; k < 4; k++) s[n][k] = 0.f;
        const uint32_t* Ku = (const uint32_t*)Ks;
        #pragma unroll
        for (int kc = 0; kc < 8; kc++) {
            #pragma unroll
            for (int n = 0; n < 8; n++) {
                uint32_t b2[2];
                b2[0] = Ku[(kc * 8 + q)     * KVPAD + n * 8 + g];
                b2[1] = Ku[(kc * 8 + q + 4) * KVPAD + n * 8 + g];
                mma_tf32(s[n], qa[kc], b2);
            }
        }

        float mx0 = NEG_BIG, mx1 = NEG_BIG;
        #pragma unroll
        for (int n = 0; n < 8; n++) {
            mx0 = fmaxf(mx0, fmaxf(s[n][0], s[n][1]));
            mx1 = fmaxf(mx1, fmaxf(s[n][2], s[n][3]));
        }
        mx0 = fmaxf(mx0, __shfl_xor_sync(0xffffffffu, mx0, 1));
        mx0 = fmaxf(mx0, __shfl_xor_sync(0xffffffffu, mx0, 2));
        mx1 = fmaxf(mx1, __shfl_xor_sync(0xffffffffu, mx1, 1));
        mx1 = fmaxf(mx1, __shfl_xor_sync(0xffffffffu, mx1, 2));
        float mn0 = fmaxf(mrow0, mx0), mn1 = fmaxf(mrow1, mx1);
        float f0 = __expf(mrow0 - mn0), f1 = __expf(mrow1 - mn1);
        mrow0 = mn0; mrow1 = mn1;
        za0 *= f0; zp0 *= f0; za1 *= f1; zp1 *= f1;
        #pragma unroll
        for (int n = 0; n < 8; n++) {
            o[n][0] *= f0; o[n][1] *= f0;
            o[n][2] *= f1; o[n][3] *= f1;
        }

        const float* M0 = Mb + (size_t)(i0 + g)     * LL + j0;
        const float* M1 = Mb + (size_t)(i0 + g + 8) * LL + j0;
        float sa0 = 0.f, sa1 = 0.f, sp0 = 0.f, sp1 = 0.f;
        uint32_t* Su = (uint32_t*)Ss;
        #pragma unroll
        for (int n = 0; n < 8; n++) {
            float2 mk0 = __ldg((const float2*)(M0 + n * 8 + q * 2));
            float2 mk1 = __ldg((const float2*)(M1 + n * 8 + q * 2));
            float e00 = __expf(s[n][0] - mn0), e01 = __expf(s[n][1] - mn0);
            float e10 = __expf(s[n][2] - mn1), e11 = __expf(s[n][3] - mn1);
            sa0 += e00 + e01; sa1 += e10 + e11;
            uint32_t p00 = f2tf(e00 * mk0.x), p01 = f2tf(e01 * mk0.y);
            uint32_t p10 = f2tf(e10 * mk1.x), p11 = f2tf(e11 * mk1.y);
            sp0 += __uint_as_float(p00) + __uint_as_float(p01);
            sp1 += __uint_as_float(p10) + __uint_as_float(p11);
            *(uint2*)&Su[(i0 + g)     * SPAD + n * 8 + q * 2] = make_uint2(p00, p01);
            *(uint2*)&Su[(i0 + g + 8) * SPAD + n * 8 + q * 2] = make_uint2(p10, p11);
        }
        sa0 += __shfl_xor_sync(0xffffffffu, sa0, 1);
        sa0 += __shfl_xor_sync(0xffffffffu, sa0, 2);
        sa1 += __shfl_xor_sync(0xffffffffu, sa1, 1);
        sa1 += __shfl_xor_sync(0xffffffffu, sa1, 2);
        sp0 += __shfl_xor_sync(0xffffffffu, sp0, 1);
        sp0 += __shfl_xor_sync(0xffffffffu, sp0, 2);
        sp1 += __shfl_xor_sync(0xffffffffu, sp1, 1);
        sp1 += __shfl_xor_sync(0xffffffffu, sp1, 2);
        za0 += sa0; za1 += sa1; zp0 += sp0; zp1 += sp1;
        __syncwarp();

        uint32_t pa[8][4];
        #pragma unroll
        for (int kc = 0; kc < 8; kc++) {
            pa[kc][0] = Su[(i0 + g)     * SPAD + kc * 8 + q];
            pa[kc][1] = Su[(i0 + g + 8) * SPAD + kc * 8 + q];
            pa[kc][2] = Su[(i0 + g)     * SPAD + kc * 8 + q + 4];
            pa[kc][3] = Su[(i0 + g + 8) * SPAD + kc * 8 + q + 4];
        }
        const uint32_t* Vu = (const uint32_t*)Vs;
        #pragma unroll
        for (int kc = 0; kc < 8; kc++) {
            #pragma unroll
            for (int n = 0; n < 8; n++) {
                uint32_t b2[2];
                b2[0] = Vu[(kc * 8 + q)     * KVPAD + n * 8 + g];
                b2[1] = Vu[(kc * 8 + q + 4) * KVPAD + n * 8 + g];
                mma_tf32(o[n], pa[kc], b2);
            }
        }
        __syncthreads();
    }

    float inv0 = 1.f / (zp0 + EPSV * za0);
    float inv1 = 1.f / (zp1 + EPSV * za1);
    float* Ob = g_z + ((size_t)b_ * LL + bi * 64) * DD + h * DHH;
    #pragma unroll
    for (int n = 0; n < 8; n++) {
        *(float2*)&Ob[(size_t)(i0 + g)     * DD + n * 8 + q * 2]
            = make_float2(o[n][0] * inv0, o[n][1] * inv0);
        *(float2*)&Ob[(size_t)(i0 + g + 8) * DD + n * 8 + q * 2]
            = make_float2(o[n][2] * inv1, o[n][3] * inv1);
    }
}

// ---------------------------------------------------------------------------
// Kernel 3: output projection (TF32 mma)  out = g_z @ W_out + b_out
// M=4096, N=1024, K=1024.
// ---------------------------------------------------------------------------
__global__ __launch_bounds__(256) void out_kernel(const float* __restrict__ W,
                                                  const float* __restrict__ bias,
                                                  float* __restrict__ out) {
    __shared__ uint32_t As[128 * APAD];
    __shared__ uint32_t Bs[32 * BPAD];
    const int bn = blockIdx.x;          // 8
    const int bm = blockIdx.y;          // 32
    const int tid = threadIdx.x;
    const int wid = tid >> 5, lane = tid & 31;
    const int g = lane >> 2, q = lane & 3;
    const int wm = wid & 3, wn = wid >> 2;

    float acc[2][8][4];
    #pragma unroll
    for (int mt = 0; mt < 2; mt++)
        #pragma unroll
        for (int nt = 0; nt < 8; nt++)
            #pragma unroll
            for (int k = 0; k < 4; k++) acc[mt][nt][k] = 0.f;

    gemm_tile_tf32(g_z + (size_t)(bm * 128) * DD, W + bn * 128,
                   DD, DD, DD / 32, As, Bs, acc);

    const int n_base = bn * 128 + wn * 64;
    #pragma unroll
    for (int mt = 0; mt < 2; mt++) {
        int m0 = bm * 128 + wm * 32 + mt * 16 + g;
        #pragma unroll
        for (int nt = 0; nt < 8; nt++) {
            int n = n_base + nt * 8 + q * 2;
            float2 bv = *(const float2*)&bias[n];
            *(float2*)&out[(size_t)m0 * DD + n]
                = make_float2(acc[mt][nt][0] + bv.x, acc[mt][nt][1] + bv.y);
            *(float2*)&out[(size_t)(m0 + 8) * DD + n]
                = make_float2(acc[mt][nt][2] + bv.x, acc[mt][nt][3] + bv.y);
        }
    }
}

// ---------------------------------------------------------------------------
extern "C" void kernel_launch(void* const* d_in, const int* in_sizes, int n_in,
                              void* d_out, int out_size) {
    const float* x    = (const float*)d_in[0];
    const float* mask = (const float*)d_in[1];
    const float* Wqkv = (const float*)d_in[2];
    const float* Wout = (const float*)d_in[3];
    const float* bout = (const float*)d_in[4];
    float* out = (float*)d_out;

    const int attn_smem = (2 * 64 * KVPAD + 64 * SPAD) * 4;  // 54272 B
    cudaFuncSetAttribute(attn_kernel,
                         cudaFuncAttributeMaxDynamicSharedMemorySize, attn_smem);

    dim3 g1(NN3 / 128, (BB * LL) / 128);
    qkv_kernel<<<g1, 256>>>(x, Wqkv);

    dim3 g2(LL / 64, HH, BB);
    attn_kernel<<<g2, 128, attn_smem>>>(mask);

    dim3 g3(DD / 128, (BB * LL) / 128);
    out_kernel<<<g3, 256>>>(Wout, bout, out);
}

// round 8
// speedup vs baseline: 2.6541x; 1.0097x over previous
#include <cuda_runtime.h>
#include <math.h>
#include <stdint.h>

#define BB   2
#define LL   2048
#define DD   1024
#define HH   16
#define DHH  64
#define NN3  3072
#define SCALEF 0.125f
#define EPSV 1e-10f
#define NEG_BIG (-1e30f)

// Scratch (static device globals; no runtime allocation allowed)
__device__ float g_q [BB*HH*LL*DHH];   // [b,h,l,dh]
__device__ float g_kT[BB*HH*DHH*LL];   // [b,h,dh,l]  (K transposed for attention)
__device__ float g_v [BB*HH*LL*DHH];   // [b,h,l,dh]
__device__ float g_z [BB*LL*DD];       // [b,l,inner]

// ---------------------------------------------------------------------------
// TF32 helpers
// ---------------------------------------------------------------------------
__device__ __forceinline__ uint32_t f2tf(float f) {
    uint32_t u;
    asm("cvt.rna.tf32.f32 %0, %1;" : "=r"(u) : "f"(f));
    return u;
}

__device__ __forceinline__ void mma_tf32(float* c, const uint32_t* a, const uint32_t* b) {
    asm volatile(
        "mma.sync.aligned.m16n8k8.row.col.f32.tf32.tf32.f32 "
        "{%0,%1,%2,%3}, {%4,%5,%6,%7}, {%8,%9}, {%0,%1,%2,%3};"
        : "+f"(c[0]), "+f"(c[1]), "+f"(c[2]), "+f"(c[3])
        : "r"(a[0]), "r"(a[1]), "r"(a[2]), "r"(a[3]), "r"(b[0]), "r"(b[1]));
}

// ---------------------------------------------------------------------------
// Shared TF32 GEMM core: 128x128 block tile, ktile=32, 256 thr (8 warps 4x2),
// warp tile 32x64. A smem [128][36], B smem [32][136] (both conflict-free).
// ---------------------------------------------------------------------------
#define APAD 36
#define BPAD 136

__device__ __forceinline__ void gemm_tile_tf32(
    const float* __restrict__ Ag,    // A block base: row-major, ld = lda
    const float* __restrict__ Bg,    // B block base: row-major, ld = ldb
    int lda, int ldb, int nktiles,
    uint32_t* As, uint32_t* Bs,      // smem
    float acc[2][8][4])
{
    const int tid = threadIdx.x;
    const int wid = tid >> 5, lane = tid & 31;
    const int g = lane >> 2, q = lane & 3;
    const int wm = wid & 3, wn = wid >> 2;

    float4 ar[4], br[4];

    // Preload ktile 0
    #pragma unroll
    for (int it = 0; it < 4; it++) {
        int idx = tid + it * 256;
        ar[it] = *(const float4*)&Ag[(size_t)(idx >> 3) * lda + ((idx & 7) << 2)];
        br[it] = *(const float4*)&Bg[(size_t)(idx >> 5) * ldb + ((idx & 31) << 2)];
    }
    #pragma unroll
    for (int it = 0; it < 4; it++) {
        int idx = tid + it * 256;
        uint32_t* ad = &As[(idx >> 3) * APAD + ((idx & 7) << 2)];
        ad[0] = f2tf(ar[it].x); ad[1] = f2tf(ar[it].y);
        ad[2] = f2tf(ar[it].z); ad[3] = f2tf(ar[it].w);
        uint32_t* bd = &Bs[(idx >> 5) * BPAD + ((idx & 31) << 2)];
        bd[0] = f2tf(br[it].x); bd[1] = f2tf(br[it].y);
        bd[2] = f2tf(br[it].z); bd[3] = f2tf(br[it].w);
    }
    __syncthreads();

    for (int kt = 0; kt < nktiles; kt++) {
        if (kt + 1 < nktiles) {
            const int k0 = (kt + 1) * 32;
            #pragma unroll
            for (int it = 0; it < 4; it++) {
                int idx = tid + it * 256;
                ar[it] = *(const float4*)&Ag[(size_t)(idx >> 3) * lda + k0 + ((idx & 7) << 2)];
                br[it] = *(const float4*)&Bg[(size_t)(k0 + (idx >> 5)) * ldb + ((idx & 31) << 2)];
            }
        }
        #pragma unroll
        for (int k8 = 0; k8 < 4; k8++) {
            uint32_t a[2][4];
            #pragma unroll
            for (int mt = 0; mt < 2; mt++) {
                int r = wm * 32 + mt * 16;
                a[mt][0] = As[(r + g)     * APAD + k8 * 8 + q];
                a[mt][1] = As[(r + g + 8) * APAD + k8 * 8 + q];
                a[mt][2] = As[(r + g)     * APAD + k8 * 8 + q + 4];
                a[mt][3] = As[(r + g + 8) * APAD + k8 * 8 + q + 4];
            }
            #pragma unroll
            for (int nt = 0; nt < 8; nt++) {
                uint32_t b2[2];
                b2[0] = Bs[(k8 * 8 + q)     * BPAD + wn * 64 + nt * 8 + g];
                b2[1] = Bs[(k8 * 8 + q + 4) * BPAD + wn * 64 + nt * 8 + g];
                mma_tf32(acc[0][nt], a[0], b2);
                mma_tf32(acc[1][nt], a[1], b2);
            }
        }
        __syncthreads();
        if (kt + 1 < nktiles) {
            #pragma unroll
            for (int it = 0; it < 4; it++) {
                int idx = tid + it * 256;
                uint32_t* ad = &As[(idx >> 3) * APAD + ((idx & 7) << 2)];
                ad[0] = f2tf(ar[it].x); ad[1] = f2tf(ar[it].y);
                ad[2] = f2tf(ar[it].z); ad[3] = f2tf(ar[it].w);
                uint32_t* bd = &Bs[(idx >> 5) * BPAD + ((idx & 31) << 2)];
                bd[0] = f2tf(br[it].x); bd[1] = f2tf(br[it].y);
                bd[2] = f2tf(br[it].z); bd[3] = f2tf(br[it].w);
            }
            __syncthreads();
        }
    }
}

// ---------------------------------------------------------------------------
// Kernel 1: QKV projection (TF32 mma), scatter into g_q / g_kT / g_v
// M=4096 (b*l), N=3072, K=1024.
// ---------------------------------------------------------------------------
__global__ __launch_bounds__(256) void qkv_kernel(const float* __restrict__ x,
                                                  const float* __restrict__ W) {
    __shared__ uint32_t As[128 * APAD];
    __shared__ uint32_t Bs[32 * BPAD];
    const int bn = blockIdx.x;          // 24
    const int bm = blockIdx.y;          // 32
    const int tid = threadIdx.x;
    const int wid = tid >> 5, lane = tid & 31;
    const int g = lane >> 2, q = lane & 3;
    const int wm = wid & 3, wn = wid >> 2;

    float acc[2][8][4];
    #pragma unroll
    for (int mt = 0; mt < 2; mt++)
        #pragma unroll
        for (int nt = 0; nt < 8; nt++)
            #pragma unroll
            for (int k = 0; k < 4; k++) acc[mt][nt][k] = 0.f;

    gemm_tile_tf32(x + (size_t)(bm * 128) * DD, W + bn * 128,
                   DD, NN3, DD / 32, As, Bs, acc);

    // Scatter: n -> (s, h, d0); whole block lies in one s (1024 % 128 == 0).
    const int n_base = bn * 128 + wn * 64;
    #pragma unroll
    for (int mt = 0; mt < 2; mt++) {
        int r0 = bm * 128 + wm * 32 + mt * 16 + g;
        int b_ = r0 >> 11;
        int l  = r0 & 2047;
        #pragma unroll
        for (int nt = 0; nt < 8; nt++) {
            int n  = n_base + nt * 8 + q * 2;
            int s  = n >> 10;
            int h  = (n >> 6) & 15;
            int d0 = n & 63;
            if (s != 1) {
                float* dst = (s == 0 ? g_q : g_v)
                           + ((size_t)(b_ * HH + h) * LL + l) * DHH + d0;
                *(float2*)dst             = make_float2(acc[mt][nt][0], acc[mt][nt][1]);
                *(float2*)(dst + 8 * DHH) = make_float2(acc[mt][nt][2], acc[mt][nt][3]);
            } else {
                float* dk = g_kT + ((size_t)(b_ * HH + h) * DHH + d0) * LL + l;
                dk[0]          = acc[mt][nt][0];
                dk[LL]         = acc[mt][nt][1];
                dk[8]          = acc[mt][nt][2];
                dk[LL + 8]     = acc[mt][nt][3];
            }
        }
    }
}

// ---------------------------------------------------------------------------
// Kernel 2: flash attention, TF32 mma. 128-query block tile, 4 warps,
// 32 query rows per warp (two 16-row m-tiles share every b-fragment load).
// jtile = 64 keys. Online softmax in registers.
// out_ij = e_ij*mask_ij / (sum_j e_ij*mask_ij + eps * sum_j e_ij)
// ---------------------------------------------------------------------------
#define KVPAD 72   // K/V smem stride: b-frag reads hit 32 distinct banks
#define SPAD  68   // P/S smem stride: a-frag reads conflict-free

__global__ __launch_bounds__(128) void attn_kernel(const float* __restrict__ mask) {
    extern __shared__ float smf[];
    float* Ks = smf;                    // [64][72] tf32 bits, row = d
    float* Vs = smf + 64 * KVPAD;       // [64][72] tf32 bits, row = j
    float* Ss = smf + 2 * 64 * KVPAD;   // [128][68] Q staging / P tile

    const int bi  = blockIdx.x;   // 16 query tiles of 128
    const int h   = blockIdx.y;   // 16
    const int b_  = blockIdx.z;   // 2
    const int tid = threadIdx.x;
    const int wid = tid >> 5, lane = tid & 31;
    const int g = lane >> 2, q = lane & 3;
    const int bh = b_ * HH + h;
    const int i0 = wid * 32;

    const float* Qb  = g_q  + ((size_t)bh * LL + bi * 128) * DHH;
    const float* KTb = g_kT + (size_t)bh * DHH * LL;
    const float* Vb  = g_v  + (size_t)bh * LL * DHH;
    const float* Mb  = mask + ((size_t)b_ * LL + bi * 128) * LL;

    // Stage Q (scale folded) into Ss: 128 rows x 64 cols.
    #pragma unroll
    for (int it = 0; it < 16; it++) {
        int idx = tid + it * 128;             // 2048 float4s
        int r = idx >> 4, c4 = (idx & 15) << 2;
        float4 v = *(const float4*)&Qb[r * DHH + c4];
        Ss[r * SPAD + c4 + 0] = v.x * SCALEF;
        Ss[r * SPAD + c4 + 1] = v.y * SCALEF;
        Ss[r * SPAD + c4 + 2] = v.z * SCALEF;
        Ss[r * SPAD + c4 + 3] = v.w * SCALEF;
    }
    __syncthreads();

    uint32_t qa[2][8][4];
    #pragma unroll
    for (int mt = 0; mt < 2; mt++) {
        int r0 = i0 + mt * 16;
        #pragma unroll
        for (int kc = 0; kc < 8; kc++) {
            qa[mt][kc][0] = f2tf(Ss[(r0 + g)     * SPAD + kc * 8 + q]);
            qa[mt][kc][1] = f2tf(Ss[(r0 + g + 8) * SPAD + kc * 8 + q]);
            qa[mt][kc][2] = f2tf(Ss[(r0 + g)     * SPAD + kc * 8 + q + 4]);
            qa[mt][kc][3] = f2tf(Ss[(r0 + g + 8) * SPAD + kc * 8 + q + 4]);
        }
    }

    float o[2][8][4];
    #pragma unroll
    for (int mt = 0; mt < 2; mt++)
        #pragma unroll
        for (int n = 0; n < 8; n++)
            #pragma unroll
            for (int k = 0; k < 4; k++) o[mt][n][k] = 0.f;
    float mrow[2][2], za[2][2], zp[2][2];
    #pragma unroll
    for (int mt = 0; mt < 2; mt++)
        #pragma unroll
        for (int hh = 0; hh < 2; hh++) {
            mrow[mt][hh] = NEG_BIG; za[mt][hh] = 0.f; zp[mt][hh] = 0.f;
        }

    for (int jt = 0; jt < 32; jt++) {
        const int j0 = jt * 64;

        // Load K (already [d][l] in gmem) and V tiles, converting to tf32.
        #pragma unroll
        for (int it = 0; it < 8; it++) {
            int idx = tid + it * 128;
            int r = idx >> 4, c4 = (idx & 15) << 2;
            float4 kv = *(const float4*)&KTb[(size_t)r * LL + j0 + c4];
            float4 vv = *(const float4*)&Vb[(size_t)(j0 + r) * DHH + c4];
            uint32_t* kd = (uint32_t*)&Ks[r * KVPAD + c4];
            kd[0] = f2tf(kv.x); kd[1] = f2tf(kv.y);
            kd[2] = f2tf(kv.z); kd[3] = f2tf(kv.w);
            uint32_t* vd = (uint32_t*)&Vs[r * KVPAD + c4];
            vd[0] = f2tf(vv.x); vd[1] = f2tf(vv.y);
            vd[2] = f2tf(vv.z); vd[3] = f2tf(vv.w);
        }
        __syncthreads();

        // S = (Q*scale) @ K^T : warp computes 32x64; b-frags shared across mt.
        float s[2][8][4];
        #pragma unroll
        for (int mt = 0; mt < 2; mt++)
            #pragma unroll
            for (int n = 0; n < 8; n++)
                #pragma unroll
                for (int k = 0; k < 4; k++) s[mt][n][k] = 0.f;
        const uint32_t* Ku = (const uint32_t*)Ks;
        #pragma unroll
        for (int kc = 0; kc < 8; kc++) {
            #pragma unroll
            for (int n = 0; n < 8; n++) {
                uint32_t b2[2];
                b2[0] = Ku[(kc * 8 + q)     * KVPAD + n * 8 + g];
                b2[1] = Ku[(kc * 8 + q + 4) * KVPAD + n * 8 + g];
                mma_tf32(s[0][n], qa[0][kc], b2);
                mma_tf32(s[1][n], qa[1][kc], b2);
            }
        }

        // Softmax update + P store, per m-tile.
        uint32_t* Su = (uint32_t*)Ss;
        #pragma unroll
        for (int mt = 0; mt < 2; mt++) {
            float mx0 = NEG_BIG, mx1 = NEG_BIG;
            #pragma unroll
            for (int n = 0; n < 8; n++) {
                mx0 = fmaxf(mx0, fmaxf(s[mt][n][0], s[mt][n][1]));
                mx1 = fmaxf(mx1, fmaxf(s[mt][n][2], s[mt][n][3]));
            }
            mx0 = fmaxf(mx0, __shfl_xor_sync(0xffffffffu, mx0, 1));
            mx0 = fmaxf(mx0, __shfl_xor_sync(0xffffffffu, mx0, 2));
            mx1 = fmaxf(mx1, __shfl_xor_sync(0xffffffffu, mx1, 1));
            mx1 = fmaxf(mx1, __shfl_xor_sync(0xffffffffu, mx1, 2));
            float mn0 = fmaxf(mrow[mt][0], mx0), mn1 = fmaxf(mrow[mt][1], mx1);
            float f0 = __expf(mrow[mt][0] - mn0), f1 = __expf(mrow[mt][1] - mn1);
            mrow[mt][0] = mn0; mrow[mt][1] = mn1;
            za[mt][0] *= f0; zp[mt][0] *= f0;
            za[mt][1] *= f1; zp[mt][1] *= f1;
            #pragma unroll
            for (int n = 0; n < 8; n++) {
                o[mt][n][0] *= f0; o[mt][n][1] *= f0;
                o[mt][n][2] *= f1; o[mt][n][3] *= f1;
            }

            const int r0 = i0 + mt * 16;
            const float* M0 = Mb + (size_t)(r0 + g)     * LL + j0;
            const float* M1 = Mb + (size_t)(r0 + g + 8) * LL + j0;
            float sa0 = 0.f, sa1 = 0.f, sp0 = 0.f, sp1 = 0.f;
            #pragma unroll
            for (int n = 0; n < 8; n++) {
                float2 mk0 = __ldg((const float2*)(M0 + n * 8 + q * 2));
                float2 mk1 = __ldg((const float2*)(M1 + n * 8 + q * 2));
                float e00 = __expf(s[mt][n][0] - mn0), e01 = __expf(s[mt][n][1] - mn0);
                float e10 = __expf(s[mt][n][2] - mn1), e11 = __expf(s[mt][n][3] - mn1);
                sa0 += e00 + e01; sa1 += e10 + e11;
                uint32_t p00 = f2tf(e00 * mk0.x), p01 = f2tf(e01 * mk0.y);
                uint32_t p10 = f2tf(e10 * mk1.x), p11 = f2tf(e11 * mk1.y);
                // sum the tf32-rounded values so numerator/denominator agree
                sp0 += __uint_as_float(p00) + __uint_as_float(p01);
                sp1 += __uint_as_float(p10) + __uint_as_float(p11);
                *(uint2*)&Su[(r0 + g)     * SPAD + n * 8 + q * 2] = make_uint2(p00, p01);
                *(uint2*)&Su[(r0 + g + 8) * SPAD + n * 8 + q * 2] = make_uint2(p10, p11);
            }
            sa0 += __shfl_xor_sync(0xffffffffu, sa0, 1);
            sa0 += __shfl_xor_sync(0xffffffffu, sa0, 2);
            sa1 += __shfl_xor_sync(0xffffffffu, sa1, 1);
            sa1 += __shfl_xor_sync(0xffffffffu, sa1, 2);
            sp0 += __shfl_xor_sync(0xffffffffu, sp0, 1);
            sp0 += __shfl_xor_sync(0xffffffffu, sp0, 2);
            sp1 += __shfl_xor_sync(0xffffffffu, sp1, 1);
            sp1 += __shfl_xor_sync(0xffffffffu, sp1, 2);
            za[mt][0] += sa0; za[mt][1] += sa1;
            zp[mt][0] += sp0; zp[mt][1] += sp1;
        }
        __syncwarp();

        // O += P @ V : load P a-frags per kc (keeps register pressure low),
        // b-frags shared across mt.
        const uint32_t* Vu = (const uint32_t*)Vs;
        #pragma unroll
        for (int kc = 0; kc < 8; kc++) {
            uint32_t pa[2][4];
            #pragma unroll
            for (int mt = 0; mt < 2; mt++) {
                int r0 = i0 + mt * 16;
                pa[mt][0] = Su[(r0 + g)     * SPAD + kc * 8 + q];
                pa[mt][1] = Su[(r0 + g + 8) * SPAD + kc * 8 + q];
                pa[mt][2] = Su[(r0 + g)     * SPAD + kc * 8 + q + 4];
                pa[mt][3] = Su[(r0 + g + 8) * SPAD + kc * 8 + q + 4];
            }
            #pragma unroll
            for (int n = 0; n < 8; n++) {
                uint32_t b2[2];
                b2[0] = Vu[(kc * 8 + q)     * KVPAD + n * 8 + g];
                b2[1] = Vu[(kc * 8 + q + 4) * KVPAD + n * 8 + g];
                mma_tf32(o[0][n], pa[0], b2);
                mma_tf32(o[1][n], pa[1], b2);
            }
        }
        __syncthreads();
    }

    // Epilogue: divide by (zm + eps*zall), write [b, l, h*64 + d].
    float* Ob = g_z + ((size_t)b_ * LL + bi * 128) * DD + h * DHH;
    #pragma unroll
    for (int mt = 0; mt < 2; mt++) {
        int r0 = i0 + mt * 16;
        float inv0 = 1.f / (zp[mt][0] + EPSV * za[mt][0]);
        float inv1 = 1.f / (zp[mt][1] + EPSV * za[mt][1]);
        #pragma unroll
        for (int n = 0; n < 8; n++) {
            *(float2*)&Ob[(size_t)(r0 + g)     * DD + n * 8 + q * 2]
                = make_float2(o[mt][n][0] * inv0, o[mt][n][1] * inv0);
            *(float2*)&Ob[(size_t)(r0 + g + 8) * DD + n * 8 + q * 2]
                = make_float2(o[mt][n][2] * inv1, o[mt][n][3] * inv1);
        }
    }
}

// ---------------------------------------------------------------------------
// Kernel 3: output projection (TF32 mma)  out = g_z @ W_out + b_out
// M=4096, N=1024, K=1024.
// ---------------------------------------------------------------------------
__global__ __launch_bounds__(256) void out_kernel(const float* __restrict__ W,
                                                  const float* __restrict__ bias,
                                                  float* __restrict__ out) {
    __shared__ uint32_t As[128 * APAD];
    __shared__ uint32_t Bs[32 * BPAD];
    const int bn = blockIdx.x;          // 8
    const int bm = blockIdx.y;          // 32
    const int tid = threadIdx.x;
    const int wid = tid >> 5, lane = tid & 31;
    const int g = lane >> 2, q = lane & 3;
    const int wm = wid & 3, wn = wid >> 2;

    float acc[2][8][4];
    #pragma unroll
    for (int mt = 0; mt < 2; mt++)
        #pragma unroll
        for (int nt = 0; nt < 8; nt++)
            #pragma unroll
            for (int k = 0; k < 4; k++) acc[mt][nt][k] = 0.f;

    gemm_tile_tf32(g_z + (size_t)(bm * 128) * DD, W + bn * 128,
                   DD, DD, DD / 32, As, Bs, acc);

    const int n_base = bn * 128 + wn * 64;
    #pragma unroll
    for (int mt = 0; mt < 2; mt++) {
        int m0 = bm * 128 + wm * 32 + mt * 16 + g;
        #pragma unroll
        for (int nt = 0; nt < 8; nt++) {
            int n = n_base + nt * 8 + q * 2;
            float2 bv = *(const float2*)&bias[n];
            *(float2*)&out[(size_t)m0 * DD + n]
                = make_float2(acc[mt][nt][0] + bv.x, acc[mt][nt][1] + bv.y);
            *(float2*)&out[(size_t)(m0 + 8) * DD + n]
                = make_float2(acc[mt][nt][2] + bv.x, acc[mt][nt][3] + bv.y);
        }
    }
}

// ---------------------------------------------------------------------------
extern "C" void kernel_launch(void* const* d_in, const int* in_sizes, int n_in,
                              void* d_out, int out_size) {
    const float* x    = (const float*)d_in[0];
    const float* mask = (const float*)d_in[1];
    const float* Wqkv = (const float*)d_in[2];
    const float* Wout = (const float*)d_in[3];
    const float* bout = (const float*)d_in[4];
    float* out = (float*)d_out;

    const int attn_smem = (2 * 64 * KVPAD + 128 * SPAD) * 4;  // 71680 B
    cudaFuncSetAttribute(attn_kernel,
                         cudaFuncAttributeMaxDynamicSharedMemorySize, attn_smem);

    dim3 g1(NN3 / 128, (BB * LL) / 128);
    qkv_kernel<<<g1, 256>>>(x, Wqkv);

    dim3 g2(LL / 128, HH, BB);
    attn_kernel<<<g2, 128, attn_smem>>>(mask);

    dim3 g3(DD / 128, (BB * LL) / 128);
    out_kernel<<<g3, 256>>>(Wout, bout, out);
}